// round 12
// baseline (speedup 1.0000x reference)
#include <cuda_runtime.h>
#include <cuda_fp16.h>
#include <cstdint>

// DistMult forward scoring:
//   score[e] = sum_d h[src[e],d] * fwd_rel[etype[e],d] * h[dst[e],d]
// E = 640000, D = 128. Index arrays are int32 on device (JAX x64 disabled).
//
// R12: the kernel is LTS-byte-bound (~345MB through L2 at ~12.9TB/s, the
// practical cap; ncu's L2% is vs a ~2x-higher theoretical peak). Cut bytes:
// group edges by src on-device (histogram -> scan -> atomic scatter), then
// one warp-pair per node loads h[src] ONCE into registers and streams only
// h[dst] per edge. h traffic: 327MB -> ~170MB.
//
// Pipeline (all graph-capturable, static __device__ scratch):
//   zero -> cvt(fp32->fp16 staging) -> hist(src) -> scan -> scatter -> main
// Scatter order within a node is nondeterministic, but each edge's score is
// computed independently and written to out[eid] -> output deterministic.

#define EMB_DIM   128
#define FULL      0xffffffffu
#define MAX_NODES 16384
#define MAX_RELS  1024
#define MAX_EDGES 1048576

__device__ __half g_h16[MAX_NODES * EMB_DIM];   // 4 MB fp16 h
__device__ __half g_w16[MAX_RELS  * EMB_DIM];   // 256 KB fp16 rel
__device__ int    g_cnt[MAX_NODES + 1];
__device__ int    g_offs[MAX_NODES + 1];
__device__ int    g_cursor[MAX_NODES + 1];
__device__ int4   g_recs[MAX_EDGES];            // (dst, etype, eid, 0)

// ---- zero the histogram ----
__global__ void zero_kernel(int n)
{
    const int i = blockIdx.x * blockDim.x + threadIdx.x;
    if (i <= n) g_cnt[i] = 0;
}

// ---- merged fp32 -> fp16 conversion, 16 floats per thread ----
__global__ __launch_bounds__(256) void cvt_merged_kernel(
    const float* __restrict__ h,
    const float* __restrict__ w,
    int n_h16, int n_tot16)
{
    const int i = blockIdx.x * blockDim.x + threadIdx.x;
    if (i >= n_tot16) return;

    const float4* in;
    uint4* out;
    if (i < n_h16) {
        in  = reinterpret_cast<const float4*>(h) + i * 4;
        out = reinterpret_cast<uint4*>(g_h16) + i * 2;
    } else {
        const int j = i - n_h16;
        in  = reinterpret_cast<const float4*>(w) + j * 4;
        out = reinterpret_cast<uint4*>(g_w16) + j * 2;
    }

    const float4 v0 = __ldcs(in + 0);
    const float4 v1 = __ldcs(in + 1);
    const float4 v2 = __ldcs(in + 2);
    const float4 v3 = __ldcs(in + 3);

    __half2 p0 = __floats2half2_rn(v0.x, v0.y);
    __half2 p1 = __floats2half2_rn(v0.z, v0.w);
    __half2 p2 = __floats2half2_rn(v1.x, v1.y);
    __half2 p3 = __floats2half2_rn(v1.z, v1.w);
    __half2 p4 = __floats2half2_rn(v2.x, v2.y);
    __half2 p5 = __floats2half2_rn(v2.z, v2.w);
    __half2 p6 = __floats2half2_rn(v3.x, v3.y);
    __half2 p7 = __floats2half2_rn(v3.z, v3.w);

    uint4 o0, o1;
    o0.x = *reinterpret_cast<uint32_t*>(&p0);
    o0.y = *reinterpret_cast<uint32_t*>(&p1);
    o0.z = *reinterpret_cast<uint32_t*>(&p2);
    o0.w = *reinterpret_cast<uint32_t*>(&p3);
    o1.x = *reinterpret_cast<uint32_t*>(&p4);
    o1.y = *reinterpret_cast<uint32_t*>(&p5);
    o1.z = *reinterpret_cast<uint32_t*>(&p6);
    o1.w = *reinterpret_cast<uint32_t*>(&p7);
    out[0] = o0;
    out[1] = o1;
}

// ---- histogram of src ----
__global__ void hist_kernel(const int* __restrict__ src, int n_edges)
{
    const int i = blockIdx.x * blockDim.x + threadIdx.x;
    if (i < n_edges) atomicAdd(&g_cnt[src[i]], 1);
}

// ---- single-block exclusive scan over g_cnt[0..n) -> g_offs / g_cursor ----
__global__ __launch_bounds__(1024) void scan_kernel(int n)
{
    __shared__ int warp_sums[32];
    __shared__ int s_carry;
    const int tid  = threadIdx.x;
    const int lane = tid & 31;
    const int wid  = tid >> 5;
    if (tid == 0) s_carry = 0;
    __syncthreads();

    for (int base = 0; base < n; base += 1024) {
        const int i = base + tid;
        int v = (i < n) ? g_cnt[i] : 0;

        int x = v;                           // warp inclusive scan
        #pragma unroll
        for (int o = 1; o < 32; o <<= 1) {
            int y = __shfl_up_sync(FULL, x, o);
            if (lane >= o) x += y;
        }
        if (lane == 31) warp_sums[wid] = x;
        __syncthreads();
        if (wid == 0) {
            int s = warp_sums[lane];
            #pragma unroll
            for (int o = 1; o < 32; o <<= 1) {
                int y = __shfl_up_sync(FULL, s, o);
                if (lane >= o) s += y;
            }
            warp_sums[lane] = s;
        }
        __syncthreads();

        const int warp_off = (wid == 0) ? 0 : warp_sums[wid - 1];
        const int excl = s_carry + warp_off + x - v;
        if (i < n) { g_offs[i] = excl; g_cursor[i] = excl; }
        __syncthreads();
        if (tid == 1023) s_carry += warp_sums[31];
        __syncthreads();
    }
    if (tid == 0) g_offs[n] = s_carry;
}

// ---- scatter edges into src-grouped record array ----
__global__ void scatter_kernel(const int* __restrict__ src,
                               const int* __restrict__ dst,
                               const int* __restrict__ etype,
                               int n_edges)
{
    const int i = blockIdx.x * blockDim.x + threadIdx.x;
    if (i >= n_edges) return;
    const int s = src[i];
    const int p = atomicAdd(&g_cursor[s], 1);
    g_recs[p] = make_int4(dst[i], etype[i], i, 0);
}

// acc2 += (u*w) * v over one uint4 triple (8 halves = 4 half2), all fp16x2.
__device__ __forceinline__ __half2 fma8_h2(uint4 u, uint4 w, uint4 v, __half2 acc2)
{
    const uint32_t* pu = reinterpret_cast<const uint32_t*>(&u);
    const uint32_t* pw = reinterpret_cast<const uint32_t*>(&w);
    const uint32_t* pv = reinterpret_cast<const uint32_t*>(&v);
    #pragma unroll
    for (int k = 0; k < 4; k++) {
        __half2 hu = *reinterpret_cast<const __half2*>(pu + k);
        __half2 hw = *reinterpret_cast<const __half2*>(pw + k);
        __half2 hv = *reinterpret_cast<const __half2*>(pv + k);
        acc2 = __hfma2(__hmul2(hu, hw), hv, acc2);
    }
    return acc2;
}

// ---- main: warp-pair per src node; hu cached in registers ----
__global__ __launch_bounds__(256) void distmult_csr_kernel(
    float* __restrict__ out, int n_nodes)
{
    const int gwarp = (blockIdx.x * blockDim.x + threadIdx.x) >> 5;
    const int node  = gwarp >> 1;       // 2 warps per node
    const int sub   = gwarp & 1;
    if (node >= n_nodes) return;

    const int lane  = threadIdx.x & 31;
    const int group = lane >> 3;        // 0..3 : record within the quad
    const int sl    = lane & 7;         // 0..7 : sub-lane within a record

    const int beg = g_offs[node];
    const int end = g_offs[node + 1];
    if (beg + sub * 4 >= end) return;   // nothing for this sub-warp (uniform)

    // h[src] row: loaded once, reused for all this node's edges.
    const uint4* __restrict__ RU =
        reinterpret_cast<const uint4*>(g_h16 + (size_t)node * EMB_DIM);
    const uint4 u0 = __ldg(RU + sl);
    const uint4 u1 = __ldg(RU + sl + 8);

    // Sub-warps interleave quads: sub 0 -> beg+0, beg+8, ...; sub 1 -> beg+4, ...
    for (int b = beg + sub * 4; b < end; b += 8) {
        const int ridx  = b + group;
        const bool valid = (ridx < end);
        const int rc = valid ? ridx : (end - 1);
        const int4 r = g_recs[rc];      // same addr across the 8-lane group

        const uint4* __restrict__ RV =
            reinterpret_cast<const uint4*>(g_h16 + (size_t)r.x * EMB_DIM);
        const uint4* __restrict__ RW =
            reinterpret_cast<const uint4*>(g_w16 + (size_t)r.y * EMB_DIM);

        const uint4 av0 = __ldcg(RV + sl);       // h[dst]: L2 stream
        const uint4 av1 = __ldcg(RV + sl + 8);
        const uint4 aw0 = __ldg (RW + sl);       // rel: L1-resident
        const uint4 aw1 = __ldg (RW + sl + 8);

        __half2 z = __float2half2_rn(0.0f);
        __half2 acc2a = fma8_h2(u0, aw0, av0, z);
        __half2 acc2b = fma8_h2(u1, aw1, av1, z);

        const float2 fa = __half22float2(acc2a);
        const float2 fb = __half22float2(acc2b);
        float acc = (fa.x + fa.y) + (fb.x + fb.y);

        acc += __shfl_xor_sync(FULL, acc, 4);
        acc += __shfl_xor_sync(FULL, acc, 2);
        acc += __shfl_xor_sync(FULL, acc, 1);

        if (valid && sl == 0) out[r.z] = acc;
    }
}

// ---- fp32 fallback for unexpected dimensions ----
__global__ __launch_bounds__(256, 8) void distmult_fp32_kernel(
    const float* __restrict__ h,
    const int* __restrict__ src,
    const int* __restrict__ dst,
    const int* __restrict__ etype,
    const float* __restrict__ fwd_rel,
    float* __restrict__ out,
    int n_edges)
{
    const int warp  = (blockIdx.x * blockDim.x + threadIdx.x) >> 5;
    const int lane  = threadIdx.x & 31;
    const int group = lane >> 3;
    const int sl    = lane & 7;

    int e = warp * 4 + group;
    const bool valid = (e < n_edges);
    if (warp * 4 >= n_edges) return;
    const int ec = valid ? e : (n_edges - 1);

    const int s = src[ec];
    const int d = dst[ec];
    const int t = etype[ec];

    const float4* __restrict__ hu = reinterpret_cast<const float4*>(h + (size_t)s * EMB_DIM);
    const float4* __restrict__ hv = reinterpret_cast<const float4*>(h + (size_t)d * EMB_DIM);
    const float4* __restrict__ wr = reinterpret_cast<const float4*>(fwd_rel + (size_t)t * EMB_DIM);

    float acc = 0.0f;
    #pragma unroll
    for (int j = 0; j < 4; j++) {
        const int idx = sl + j * 8;
        const float4 a = __ldcg(hu + idx);
        const float4 c = __ldcg(hv + idx);
        const float4 b = __ldg(wr + idx);
        float p = a.x * b.x * c.x;
        p = fmaf(a.y * b.y, c.y, p);
        p = fmaf(a.z * b.z, c.z, p);
        p = fmaf(a.w * b.w, c.w, p);
        acc += p;
    }
    acc += __shfl_xor_sync(FULL, acc, 4);
    acc += __shfl_xor_sync(FULL, acc, 2);
    acc += __shfl_xor_sync(FULL, acc, 1);
    if (valid && sl == 0) out[e] = acc;
}

extern "C" void kernel_launch(void* const* d_in, const int* in_sizes, int n_in,
                              void* d_out, int out_size)
{
    const float* h       = (const float*)d_in[0];
    const int*   src     = (const int*)d_in[1];
    const int*   dst     = (const int*)d_in[2];
    const int*   etype   = (const int*)d_in[3];
    const float* fwd_rel = (const float*)d_in[4];
    // d_in[5] = rev_rel, unused in forward scoring.
    float* out = (float*)d_out;

    const int n_edges = in_sizes[1];
    const int h_elems = in_sizes[0];
    const int w_elems = in_sizes[4];
    const int n_nodes = h_elems / EMB_DIM;

    if (h_elems % EMB_DIM != 0 || n_nodes > MAX_NODES ||
        w_elems > MAX_RELS * EMB_DIM || (w_elems & 15) ||
        n_edges > MAX_EDGES) {
        const int blocks = (n_edges + 31) / 32;
        distmult_fp32_kernel<<<blocks, 256>>>(h, src, dst, etype, fwd_rel,
                                              out, n_edges);
        return;
    }

    const int n_h16   = h_elems / 16;
    const int n_tot16 = n_h16 + w_elems / 16;
    const int eb      = (n_edges + 255) / 256;

    zero_kernel<<<(n_nodes + 256) / 256, 256>>>(n_nodes);
    cvt_merged_kernel<<<(n_tot16 + 255) / 256, 256>>>(h, fwd_rel, n_h16, n_tot16);
    hist_kernel<<<eb, 256>>>(src, n_edges);
    scan_kernel<<<1, 1024>>>(n_nodes);
    scatter_kernel<<<eb, 256>>>(src, dst, etype, n_edges);

    // 2 warps per node, 8 warps per block.
    const int warps  = 2 * n_nodes;
    const int blocks = (warps + 7) / 8;
    distmult_csr_kernel<<<blocks, 256>>>(out, n_nodes);
}